// round 5
// baseline (speedup 1.0000x reference)
#include <cuda_runtime.h>

// ConjunctionLayer: out[b,j] = -1/(-1 + sum_k log(1 - (1-x[b,k]) * W[j,k]))
// B=4096, D=512, N=128, fp32.
//
// sum(log Z) == log(prod Z), Z in (0.5, 1]: FMUL product chains, one log2 per
// 64 k's (min 0.5^64, still normal fp32). Packed f32x2 math, even k in lo
// lane / odd k in hi lane. 128-thread CTAs, TB=8 -> 512 CTAs for occupancy.
// W smem XOR-swizzled (column ^ (row>>2)&7) -> conflict-free LDS.128.

#define Bdim 4096
#define Ddim 512
#define Ndim 128

#define TB    8            // b-rows per CTA -> 512 CTAs
#define KC    32           // k per staged chunk (128B rows)
#define NCH   (Ddim / KC)  // 16
#define SROWX 36           // sx row stride (words): pad for conflict-free rows
#define XW    (TB * SROWX)         // 288 words
#define SWROW 32                   // sw row stride (words) = 128B, swizzled
#define BUFW  (XW + Ndim * SWROW)  // 288 + 4096 = 4384 words / buffer

typedef unsigned long long ull;

__device__ __forceinline__ ull fma2(ull a, ull b, ull c) {
    ull d; asm("fma.rn.f32x2 %0, %1, %2, %3;" : "=l"(d) : "l"(a), "l"(b), "l"(c));
    return d;
}
__device__ __forceinline__ ull mul2(ull a, ull b) {
    ull d; asm("mul.rn.f32x2 %0, %1, %2;" : "=l"(d) : "l"(a), "l"(b));
    return d;
}
__device__ __forceinline__ ull add2(ull a, ull b) {
    ull d; asm("add.rn.f32x2 %0, %1, %2;" : "=l"(d) : "l"(a), "l"(b));
    return d;
}
__device__ __forceinline__ void unpack2(ull v, float& lo, float& hi) {
    asm("mov.b64 {%0, %1}, %2;" : "=f"(lo), "=f"(hi) : "l"(v));
}
__device__ __forceinline__ void cp16(unsigned smem_dst, const void* gsrc) {
    asm volatile("cp.async.cg.shared.global [%0], [%1], 16;\n"
                 :: "r"(smem_dst), "l"(gsrc));
}

__global__ __launch_bounds__(128, 6)
void conj_kernel(const float* __restrict__ x,
                 const float* __restrict__ W,
                 float* __restrict__ out) {
    __shared__ float smem[2 * BUFW];   // [buf][ sx(8x36) | sw(128x32, swizzled) ]

    const int tid   = threadIdx.x;
    const int b_blk = blockIdx.x * TB;
    const int tj    = tid >> 2;        // 0..31 -> j group (j0 = 4*tj)
    const int tb    = tid & 3;         // 0..3  -> b rows tb, tb+4
    const int j0    = tj * 4;
    const int tj7   = tj & 7;          // W swizzle key for this thread's rows

    const ull ONE2  = 0x3F8000003F800000ull;   // {1.0f, 1.0f}
    const ull NONE2 = 0xBF800000BF800000ull;   // {-1.0f, -1.0f}

    ull   prod[2][4];
    float lsum[2][4];
#pragma unroll
    for (int r = 0; r < 2; r++)
#pragma unroll
        for (int c = 0; c < 4; c++) { prod[r][c] = ONE2; lsum[r][c] = 0.0f; }

    const unsigned sbase = (unsigned)__cvta_generic_to_shared(smem);

    // W staging map: 1024 float4 per chunk, 8 per thread, XOR-swizzled column
    int wrow[8], wc4[8], wc4s[8];
#pragma unroll
    for (int t = 0; t < 8; t++) {
        int idx = tid + t * 128;
        wrow[t] = idx >> 3;
        wc4[t]  = idx & 7;
        wc4s[t] = wc4[t] ^ ((wrow[t] >> 2) & 7);
    }
    // x staging map: 64 float4 per chunk, threads 0..63
    const int xrow = tid >> 3;
    const int xc4  = tid & 7;

#define STAGE(CH, P)                                                          \
    do {                                                                      \
        int k0 = (CH) * KC;                                                   \
        unsigned bofs = sbase + (P) * (BUFW * 4);                             \
        _Pragma("unroll")                                                     \
        for (int t = 0; t < 8; t++)                                           \
            cp16(bofs + (XW + wrow[t] * SWROW + wc4s[t] * 4) * 4,             \
                 &W[wrow[t] * Ddim + k0 + wc4[t] * 4]);                       \
        if (tid < 64)                                                         \
            cp16(bofs + (xrow * SROWX + xc4 * 4) * 4,                         \
                 &x[(b_blk + xrow) * Ddim + k0 + xc4 * 4]);                   \
        asm volatile("cp.async.commit_group;");                               \
    } while (0)

    STAGE(0, 0);

    for (int ch = 0; ch < NCH; ch++) {
        const int p = ch & 1;
        asm volatile("cp.async.wait_group 0;");
        __syncthreads();                 // buf p full; buf p^1 fully consumed
        if (ch + 1 < NCH) STAGE(ch + 1, p ^ 1);

        const float* bx = &smem[p * BUFW];
        const float* bw = &smem[p * BUFW + XW + j0 * SWROW];

#pragma unroll
        for (int kk = 0; kk < KC; kk += 4) {
            ulonglong2 av0 = *(const ulonglong2*)&bx[tb * SROWX + kk];
            ulonglong2 av1 = *(const ulonglong2*)&bx[(tb + 4) * SROWX + kk];
            ull a0x = add2(av0.x, NONE2), a0y = add2(av0.y, NONE2);
            ull a1x = add2(av1.x, NONE2), a1y = add2(av1.y, NONE2);
            const float* wp = bw + ((((kk >> 2) ^ tj7) << 2));
#pragma unroll
            for (int c = 0; c < 4; c++) {
                ulonglong2 wv = *(const ulonglong2*)&wp[c * SWROW];
                prod[0][c] = mul2(prod[0][c], fma2(a0x, wv.x, ONE2));
                prod[0][c] = mul2(prod[0][c], fma2(a0y, wv.y, ONE2));
                prod[1][c] = mul2(prod[1][c], fma2(a1x, wv.x, ONE2));
                prod[1][c] = mul2(prod[1][c], fma2(a1y, wv.y, ONE2));
            }
        }

        if (ch & 1) {  // flush every 64 k's: per-lane min 0.5^32, merged 0.5^64
#pragma unroll
            for (int r = 0; r < 2; r++)
#pragma unroll
                for (int c = 0; c < 4; c++) {
                    float lo, hi;
                    unpack2(prod[r][c], lo, hi);
                    lsum[r][c] += __log2f(lo * hi);
                    prod[r][c] = ONE2;
                }
        }
    }

    // epilogue: y = -1 / (-1 + ln2 * sum_log2)
    const float LN2 = 0.6931471805599453f;
#pragma unroll
    for (int r = 0; r < 2; r++) {
        int b = b_blk + tb + r * 4;
        float v[4];
#pragma unroll
        for (int c = 0; c < 4; c++) {
            float s = lsum[r][c] * LN2;
            v[c] = __fdividef(-1.0f, s - 1.0f);
        }
        *(float4*)&out[b * Ndim + j0] = make_float4(v[0], v[1], v[2], v[3]);
    }
}

extern "C" void kernel_launch(void* const* d_in, const int* in_sizes, int n_in,
                              void* d_out, int out_size) {
    const float* x = (const float*)d_in[0];   // (4096, 512)
    const float* W = (const float*)d_in[1];   // (128, 512)
    float* out = (float*)d_out;               // (4096, 128)
    (void)in_sizes; (void)n_in; (void)out_size;

    dim3 grid(Bdim / TB);   // 512 CTAs
    dim3 block(128);
    conj_kernel<<<grid, block>>>(x, W, out);
}

// round 6
// speedup vs baseline: 1.0651x; 1.0651x over previous
#include <cuda_runtime.h>

// ConjunctionLayer: out[b,j] = -1/(-1 + sum_k log(1 - (1-x[b,k]) * W[j,k]))
// B=4096, D=512, N=128, fp32.
//
// sum(log Z) == log(prod Z), Z in (0.5, 1]: FMUL product chains, one log2 per
// 64 k's. Packed f32x2 math (even k lo lane / odd k hi lane). 2-way K-split:
// each CTA reduces 256 k's for an 8-row b-tile -> 1024 CTAs (2x warps vs R5),
// partial log2-sums in __device__ scratch, tiny combine kernel finishes.

#define Bdim 4096
#define Ddim 512
#define Ndim 128

#define KSPLIT 2
#define KHALF  (Ddim / KSPLIT)   // 256
#define TB     8                 // b-rows per CTA
#define KC     32                // k per staged chunk (128B rows)
#define NCH    (KHALF / KC)      // 8 chunks per CTA
#define SROWX  36                // sx row stride (words)
#define XW     (TB * SROWX)      // 288 words
#define SWROW  32                // sw row stride (words), XOR-swizzled
#define BUFW   (XW + Ndim * SWROW)   // 4384 words / buffer

__device__ float g_partial[KSPLIT][Bdim * Ndim];   // log2 partial sums (4MB)

typedef unsigned long long ull;

__device__ __forceinline__ ull fma2(ull a, ull b, ull c) {
    ull d; asm("fma.rn.f32x2 %0, %1, %2, %3;" : "=l"(d) : "l"(a), "l"(b), "l"(c));
    return d;
}
__device__ __forceinline__ ull mul2(ull a, ull b) {
    ull d; asm("mul.rn.f32x2 %0, %1, %2;" : "=l"(d) : "l"(a), "l"(b));
    return d;
}
__device__ __forceinline__ ull add2(ull a, ull b) {
    ull d; asm("add.rn.f32x2 %0, %1, %2;" : "=l"(d) : "l"(a), "l"(b));
    return d;
}
__device__ __forceinline__ void unpack2(ull v, float& lo, float& hi) {
    asm("mov.b64 {%0, %1}, %2;" : "=f"(lo), "=f"(hi) : "l"(v));
}
__device__ __forceinline__ void cp16(unsigned smem_dst, const void* gsrc) {
    asm volatile("cp.async.cg.shared.global [%0], [%1], 16;\n"
                 :: "r"(smem_dst), "l"(gsrc));
}

__global__ __launch_bounds__(128, 6)
void conj_main(const float* __restrict__ x,
               const float* __restrict__ W) {
    __shared__ float smem[2 * BUFW];   // [buf][ sx(8x36) | sw(128x32, swizzled) ]

    const int tid   = threadIdx.x;
    const int bx    = blockIdx.x;
    const int ks    = bx & 1;                 // K-split half
    const int b_blk = (bx >> 1) * TB;
    const int kbase = ks * KHALF;
    const int tj    = tid >> 2;               // 0..31 -> j group (j0 = 4*tj)
    const int tb    = tid & 3;                // 0..3  -> b rows tb, tb+4
    const int j0    = tj * 4;
    const int tj7   = tj & 7;                 // W swizzle key

    const ull ONE2  = 0x3F8000003F800000ull;  // {1.0f, 1.0f}
    const ull NONE2 = 0xBF800000BF800000ull;  // {-1.0f, -1.0f}

    ull   prod[2][4];
    float lsum[2][4];
#pragma unroll
    for (int r = 0; r < 2; r++)
#pragma unroll
        for (int c = 0; c < 4; c++) { prod[r][c] = ONE2; lsum[r][c] = 0.0f; }

    const unsigned sbase = (unsigned)__cvta_generic_to_shared(smem);

    // W staging: 1024 float4 per chunk, 8 per thread, XOR-swizzled column
    int wrow[8], wc4[8], wc4s[8];
#pragma unroll
    for (int t = 0; t < 8; t++) {
        int idx = tid + t * 128;
        wrow[t] = idx >> 3;
        wc4[t]  = idx & 7;
        wc4s[t] = wc4[t] ^ ((wrow[t] >> 2) & 7);
    }
    // x staging: 64 float4 per chunk, threads 0..63
    const int xrow = tid >> 3;
    const int xc4  = tid & 7;

#define STAGE(CH, P)                                                          \
    do {                                                                      \
        int k0 = kbase + (CH) * KC;                                           \
        unsigned bofs = sbase + (P) * (BUFW * 4);                             \
        _Pragma("unroll")                                                     \
        for (int t = 0; t < 8; t++)                                           \
            cp16(bofs + (XW + wrow[t] * SWROW + wc4s[t] * 4) * 4,             \
                 &W[wrow[t] * Ddim + k0 + wc4[t] * 4]);                       \
        if (tid < 64)                                                         \
            cp16(bofs + (xrow * SROWX + xc4 * 4) * 4,                         \
                 &x[(b_blk + xrow) * Ddim + k0 + xc4 * 4]);                   \
        asm volatile("cp.async.commit_group;");                               \
    } while (0)

    STAGE(0, 0);

    for (int ch = 0; ch < NCH; ch++) {
        const int p = ch & 1;
        asm volatile("cp.async.wait_group 0;");
        __syncthreads();                 // buf p full; buf p^1 fully consumed
        if (ch + 1 < NCH) STAGE(ch + 1, p ^ 1);

        const float* bx_s = &smem[p * BUFW];
        const float* bw_s = &smem[p * BUFW + XW + j0 * SWROW];

#pragma unroll
        for (int kk = 0; kk < KC; kk += 4) {
            ulonglong2 av0 = *(const ulonglong2*)&bx_s[tb * SROWX + kk];
            ulonglong2 av1 = *(const ulonglong2*)&bx_s[(tb + 4) * SROWX + kk];
            ull a0x = add2(av0.x, NONE2), a0y = add2(av0.y, NONE2);
            ull a1x = add2(av1.x, NONE2), a1y = add2(av1.y, NONE2);
            const float* wp = bw_s + ((((kk >> 2) ^ tj7) << 2));
#pragma unroll
            for (int c = 0; c < 4; c++) {
                ulonglong2 wv = *(const ulonglong2*)&wp[c * SWROW];
                prod[0][c] = mul2(prod[0][c], fma2(a0x, wv.x, ONE2));
                prod[0][c] = mul2(prod[0][c], fma2(a0y, wv.y, ONE2));
                prod[1][c] = mul2(prod[1][c], fma2(a1x, wv.x, ONE2));
                prod[1][c] = mul2(prod[1][c], fma2(a1y, wv.y, ONE2));
            }
        }

        if (ch & 1) {  // flush every 64 k's: merged product >= 0.5^64, normal
#pragma unroll
            for (int r = 0; r < 2; r++)
#pragma unroll
                for (int c = 0; c < 4; c++) {
                    float lo, hi;
                    unpack2(prod[r][c], lo, hi);
                    lsum[r][c] += __log2f(lo * hi);
                    prod[r][c] = ONE2;
                }
        }
    }

    // write partial log2 sums
    float* part = &g_partial[ks][0];
#pragma unroll
    for (int r = 0; r < 2; r++) {
        int b = b_blk + tb + r * 4;
        *(float4*)&part[b * Ndim + j0] =
            make_float4(lsum[r][0], lsum[r][1], lsum[r][2], lsum[r][3]);
    }
}

__global__ __launch_bounds__(256)
void conj_combine(float* __restrict__ out) {
    const float LN2 = 0.6931471805599453f;
    int i = (blockIdx.x * 256 + threadIdx.x) * 4;   // float4 granularity
    float4 s0 = *(const float4*)&g_partial[0][i];
    float4 s1 = *(const float4*)&g_partial[1][i];
    float4 v;
    v.x = __fdividef(-1.0f, (s0.x + s1.x) * LN2 - 1.0f);
    v.y = __fdividef(-1.0f, (s0.y + s1.y) * LN2 - 1.0f);
    v.z = __fdividef(-1.0f, (s0.z + s1.z) * LN2 - 1.0f);
    v.w = __fdividef(-1.0f, (s0.w + s1.w) * LN2 - 1.0f);
    *(float4*)&out[i] = v;
}

extern "C" void kernel_launch(void* const* d_in, const int* in_sizes, int n_in,
                              void* d_out, int out_size) {
    const float* x = (const float*)d_in[0];   // (4096, 512)
    const float* W = (const float*)d_in[1];   // (128, 512)
    float* out = (float*)d_out;               // (4096, 128)
    (void)in_sizes; (void)n_in; (void)out_size;

    conj_main<<<(Bdim / TB) * KSPLIT, 128>>>(x, W);          // 1024 CTAs
    conj_combine<<<(Bdim * Ndim) / (256 * 4), 256>>>(out);   // 512 CTAs
}

// round 8
// speedup vs baseline: 1.1493x; 1.0790x over previous
#include <cuda_runtime.h>

// ConjunctionLayer: out[b,j] = -1/(-1 + sum_k log(1 - (1-x[b,k]) * W[j,k]))
// B=4096, D=512, N=128, fp32.
//
// sum(log Z) == log(prod Z), Z in (0.5, 1]: FMUL product chains, one log2 per
// 64 k's. Packed f32x2 math. 2-way K-split fused via 2-CTA clusters: rank r
// reduces k in [r*256, r*256+256); partials exchanged through smem + DSMEM,
// each rank finalizes half the b-rows. No scratch, no second kernel.

#define Bdim 4096
#define Ddim 512
#define Ndim 128

#define KSPLIT 2
#define KHALF  (Ddim / KSPLIT)   // 256
#define TB     8                 // b-rows per tile
#define KC     32                // k per staged chunk (128B rows)
#define NCH    (KHALF / KC)      // 8 chunks per CTA
#define SROWX  36                // sx row stride (words)
#define XW     (TB * SROWX)      // 288 words
#define SWROW  32                // sw row stride (words), XOR-swizzled
#define BUFW   (XW + Ndim * SWROW)   // 4384 words / buffer

typedef unsigned long long ull;

__device__ __forceinline__ ull fma2(ull a, ull b, ull c) {
    ull d; asm("fma.rn.f32x2 %0, %1, %2, %3;" : "=l"(d) : "l"(a), "l"(b), "l"(c));
    return d;
}
__device__ __forceinline__ ull mul2(ull a, ull b) {
    ull d; asm("mul.rn.f32x2 %0, %1, %2;" : "=l"(d) : "l"(a), "l"(b));
    return d;
}
__device__ __forceinline__ void unpack2(ull v, float& lo, float& hi) {
    asm("mov.b64 {%0, %1}, %2;" : "=f"(lo), "=f"(hi) : "l"(v));
}
__device__ __forceinline__ void cp16(unsigned smem_dst, const void* gsrc) {
    asm volatile("cp.async.cg.shared.global [%0], [%1], 16;\n"
                 :: "r"(smem_dst), "l"(gsrc));
}

__global__ __launch_bounds__(128, 6) __cluster_dims__(2, 1, 1)
void conj_kernel(const float* __restrict__ x,
                 const float* __restrict__ W,
                 float* __restrict__ out) {
    __shared__ float smem[2 * BUFW];   // staging; first 1024 words reused as partials

    const int tid   = threadIdx.x;
    unsigned rank;
    asm("mov.u32 %0, %%cluster_ctarank;" : "=r"(rank));
    const int b_blk = (blockIdx.x >> 1) * TB;
    const int kbase = (int)rank * KHALF;
    const int tj    = tid >> 2;               // 0..31 -> j group (j0 = 4*tj)
    const int tb    = tid & 3;                // 0..3  -> b rows tb, tb+4
    const int j0    = tj * 4;
    const int tj7   = tj & 7;                 // W swizzle key

    const ull ONE2 = 0x3F8000003F800000ull;   // {1.0f, 1.0f}

    ull   prod[2][4];
    float lsum[2][4];
#pragma unroll
    for (int r = 0; r < 2; r++)
#pragma unroll
        for (int c = 0; c < 4; c++) { prod[r][c] = ONE2; lsum[r][c] = 0.0f; }

    const unsigned sbase = (unsigned)__cvta_generic_to_shared(smem);

    // W staging: 1024 float4 per chunk, 8 per thread, XOR-swizzled column
    int wrow[8], wc4[8], wc4s[8];
#pragma unroll
    for (int t = 0; t < 8; t++) {
        int idx = tid + t * 128;
        wrow[t] = idx >> 3;
        wc4[t]  = idx & 7;
        wc4s[t] = wc4[t] ^ ((wrow[t] >> 2) & 7);
    }
    // x staging: 64 float4 per chunk via registers (a = x-1 folded), threads 0..63
    const int xrow = tid >> 3;
    const int xc4  = tid & 7;
    const bool xth = (tid < 64);

#define STAGE_W(CH, P)                                                        \
    do {                                                                      \
        int k0 = kbase + (CH) * KC;                                           \
        unsigned bofs = sbase + (P) * (BUFW * 4);                             \
        _Pragma("unroll")                                                     \
        for (int t = 0; t < 8; t++)                                           \
            cp16(bofs + (XW + wrow[t] * SWROW + wc4s[t] * 4) * 4,             \
                 &W[wrow[t] * Ddim + k0 + wc4[t] * 4]);                       \
        asm volatile("cp.async.commit_group;");                               \
    } while (0)

#define LDG_X(CH, DST)                                                        \
    do {                                                                      \
        if (xth) {                                                            \
            float4 v = *(const float4*)&x[(b_blk + xrow) * Ddim +             \
                                          kbase + (CH) * KC + xc4 * 4];       \
            (DST) = make_float4(v.x - 1.0f, v.y - 1.0f, v.z - 1.0f, v.w - 1.0f); \
        }                                                                     \
    } while (0)

#define STS_X(P, SRC)                                                         \
    do {                                                                      \
        if (xth)                                                              \
            *(float4*)&smem[(P) * BUFW + xrow * SROWX + xc4 * 4] = (SRC);     \
    } while (0)

    // prologue: x0 -> buf0, W0 in flight, x1 in regs
    float4 pxa, pxb;
    LDG_X(0, pxa);
    STS_X(0, pxa);
    STAGE_W(0, 0);
    LDG_X(1, pxa);

    for (int ch = 0; ch < NCH; ch++) {
        const int p = ch & 1;
        asm volatile("cp.async.wait_group 0;");
        __syncthreads();            // buf p complete (W + x); buf p^1 consumed

        if (ch + 1 < NCH) {
            STS_X(p ^ 1, pxa);
            STAGE_W(ch + 1, p ^ 1);
            if (ch + 2 < NCH) LDG_X(ch + 2, pxb);
        }

        const float* bx_s = &smem[p * BUFW];
        const float* bw_s = &smem[p * BUFW + XW + j0 * SWROW];

#pragma unroll
        for (int kk = 0; kk < KC; kk += 4) {
            ulonglong2 av0 = *(const ulonglong2*)&bx_s[tb * SROWX + kk];
            ulonglong2 av1 = *(const ulonglong2*)&bx_s[(tb + 4) * SROWX + kk];
            const float* wp = bw_s + ((((kk >> 2) ^ tj7) << 2));
#pragma unroll
            for (int c = 0; c < 4; c++) {
                ulonglong2 wv = *(const ulonglong2*)&wp[c * SWROW];
                prod[0][c] = mul2(prod[0][c], fma2((ull)av0.x, wv.x, ONE2));
                prod[0][c] = mul2(prod[0][c], fma2((ull)av0.y, wv.y, ONE2));
                prod[1][c] = mul2(prod[1][c], fma2((ull)av1.x, wv.x, ONE2));
                prod[1][c] = mul2(prod[1][c], fma2((ull)av1.y, wv.y, ONE2));
            }
        }

        if (ch & 1) {  // flush every 64 k's: merged product >= 0.5^64, normal
#pragma unroll
            for (int r = 0; r < 2; r++)
#pragma unroll
                for (int c = 0; c < 4; c++) {
                    float lo, hi;
                    unpack2(prod[r][c], lo, hi);
                    lsum[r][c] += __log2f(lo * hi);
                    prod[r][c] = ONE2;
                }
        }
        pxa = pxb;
    }

    // ---- partial exchange via cluster smem ----
    // part[row][j], row 0..7 => b = b_blk + row  (overlay on dead buf0 region)
    float* part = smem;
#pragma unroll
    for (int r = 0; r < 2; r++)
        *(float4*)&part[(tb + r * 4) * Ndim + j0] =
            make_float4(lsum[r][0], lsum[r][1], lsum[r][2], lsum[r][3]);

    asm volatile("barrier.cluster.arrive.aligned;" ::: "memory");
    asm volatile("barrier.cluster.wait.aligned;" ::: "memory");

    // rank r finalizes rows r*4 .. r*4+3 (one float4 per thread)
    {
        const float LN2 = 0.6931471805599453f;
        int fofs = ((int)rank * 512 + tid * 4);         // float index into part
        int row  = fofs >> 7;
        int col  = fofs & 127;

        unsigned own_addr  = sbase + fofs * 4;
        unsigned peer_addr;
        asm("mapa.shared::cluster.u32 %0, %1, %2;"
            : "=r"(peer_addr) : "r"(own_addr), "r"(rank ^ 1u));

        float4 s0 = *(const float4*)&part[fofs];
        float  p0, p1, p2, p3;
        asm volatile("ld.shared::cluster.v4.f32 {%0, %1, %2, %3}, [%4];"
                     : "=f"(p0), "=f"(p1), "=f"(p2), "=f"(p3) : "r"(peer_addr));

        float4 v;
        v.x = __fdividef(-1.0f, (s0.x + p0) * LN2 - 1.0f);
        v.y = __fdividef(-1.0f, (s0.y + p1) * LN2 - 1.0f);
        v.z = __fdividef(-1.0f, (s0.z + p2) * LN2 - 1.0f);
        v.w = __fdividef(-1.0f, (s0.w + p3) * LN2 - 1.0f);
        *(float4*)&out[(b_blk + row) * Ndim + col] = v;
    }

    // peer may still be reading our smem — hold until whole cluster is done
    asm volatile("barrier.cluster.arrive.aligned;" ::: "memory");
    asm volatile("barrier.cluster.wait.aligned;" ::: "memory");
}

extern "C" void kernel_launch(void* const* d_in, const int* in_sizes, int n_in,
                              void* d_out, int out_size) {
    const float* x = (const float*)d_in[0];   // (4096, 512)
    const float* W = (const float*)d_in[1];   // (128, 512)
    float* out = (float*)d_out;               // (4096, 128)
    (void)in_sizes; (void)n_in; (void)out_size;

    conj_kernel<<<(Bdim / TB) * KSPLIT, 128>>>(x, W, out);   // 1024 CTAs, clusters of 2
}